// round 12
// baseline (speedup 1.0000x reference)
#include <cuda_runtime.h>
#include <cuda_fp16.h>
#include <math.h>
#include <stdint.h>

#define DIMM   2048
#define NHEAD  16
#define HDIM   128
#define SEQ    2048
#define BATCH  2
#define MTOK   (BATCH*SEQ)   // 4096 tokens
#define WSZ    ((size_t)DIMM * DIMM)

// ---------------------------------------------------------------------------
// Device-global scratch (no allocation allowed)
// ---------------------------------------------------------------------------
__device__ __half g_x16[(size_t)MTOK * DIMM];   // x, fp16 only
__device__ __half g_W[4][WSZ];                  // weights, fp16 only
__device__ __half g_Qh[(size_t)MTOK * DIMM];
__device__ __half g_Ql[(size_t)MTOK * DIMM];
__device__ __half g_Kh[(size_t)MTOK * DIMM];    // fp16 only
__device__ __half g_Vh[(size_t)MTOK * DIMM];    // fp16 only
__device__ __half g_Ah[(size_t)MTOK * DIMM];    // flash out, fp16 only

__device__ float2 g_rt[SEQ * 64];   // RoPE cos/sin table

// ---------------------------------------------------------------------------
// PTX helpers
// ---------------------------------------------------------------------------
__device__ __forceinline__ uint32_t sm_u32(const void* p) {
    return (uint32_t)__cvta_generic_to_shared(p);
}
__device__ __forceinline__ void cp16(uint32_t dst, const void* src) {
    asm volatile("cp.async.cg.shared.global [%0], [%1], 16;" :: "r"(dst), "l"(src) : "memory");
}
__device__ __forceinline__ void ldsm_x4(uint32_t* r, uint32_t a) {
    asm volatile("ldmatrix.sync.aligned.m8n8.x4.shared.b16 {%0,%1,%2,%3}, [%4];"
                 : "=r"(r[0]), "=r"(r[1]), "=r"(r[2]), "=r"(r[3]) : "r"(a));
}
__device__ __forceinline__ void ldsm_x4t(uint32_t* r, uint32_t a) {
    asm volatile("ldmatrix.sync.aligned.m8n8.x4.trans.shared.b16 {%0,%1,%2,%3}, [%4];"
                 : "=r"(r[0]), "=r"(r[1]), "=r"(r[2]), "=r"(r[3]) : "r"(a));
}
__device__ __forceinline__ void mma_f16(float* c, const uint32_t* a,
                                        uint32_t b0, uint32_t b1) {
    asm volatile(
        "mma.sync.aligned.m16n8k16.row.col.f32.f16.f16.f32 "
        "{%0,%1,%2,%3}, {%4,%5,%6,%7}, {%8,%9}, {%0,%1,%2,%3};"
        : "+f"(c[0]), "+f"(c[1]), "+f"(c[2]), "+f"(c[3])
        : "r"(a[0]), "r"(a[1]), "r"(a[2]), "r"(a[3]), "r"(b0), "r"(b1));
}
__device__ __forceinline__ float fexp2(float x) {
    float y;
    asm("ex2.approx.ftz.f32 %0, %1;" : "=f"(y) : "f"(x));
    return y;
}
__device__ __forceinline__ uint32_t packh2(float f0, float f1) {
    __half2 h = __floats2half2_rn(f0, f1);
    return *(uint32_t*)&h;
}
__device__ __forceinline__ void split2h(float f0, float f1,
                                        uint32_t& hi, uint32_t& lo) {
    __half2 h = __floats2half2_rn(f0, f1);
    float2 fb = __half22float2(h);
    __half2 l = __floats2half2_rn(f0 - fb.x, f1 - fb.y);
    hi = *(uint32_t*)&h;
    lo = *(uint32_t*)&l;
}

extern __shared__ __half gsm[];

// ---------------------------------------------------------------------------
// Convert fp32 -> fp16
// ---------------------------------------------------------------------------
__global__ __launch_bounds__(256) void convert_kernel(
    const float* __restrict__ src, __half* __restrict__ dst, int n)
{
    int i = (blockIdx.x * blockDim.x + threadIdx.x) * 4;
    if (i >= n) return;
    float4 v = *(const float4*)(src + i);
    *(uint32_t*)(dst + i)     = packh2(v.x, v.y);
    *(uint32_t*)(dst + i + 2) = packh2(v.z, v.w);
}

// ---------------------------------------------------------------------------
// RoPE table (double precision)
// ---------------------------------------------------------------------------
__global__ __launch_bounds__(256) void rope_table_kernel()
{
    int idx = blockIdx.x * blockDim.x + threadIdx.x;
    if (idx >= SEQ * 64) return;
    int pos = idx >> 6, i = idx & 63;
    double invf = pow(10000.0, -(double)i / 64.0);
    double sd, cd;
    sincos((double)pos * invf, &sd, &cd);
    g_rt[idx] = make_float2((float)cd, (float)sd);
}

// ---------------------------------------------------------------------------
// fp16 GEMM (1 mma): CTA 128x256, BK=32, 8 warps of 64x64, 4-stage cp.async.
// A fp16 [M,K], B = W fp16 [K,N] row-major (ldsm trans).
// job==1 (QKV fused, blockIdx.x selects region):
//   region 0 (Q): bias + rope + qscale + fp16 hi/lo split
//   region 1 (K): bias + rope + fp16 ; region 2 (V): bias + fp16
// job==0 (O): bias + fp32 store.
// ---------------------------------------------------------------------------
#define SAH 0
#define SBH 5120
#define ST4_SZ 13568               // fp16 elems per stage (27136 B)
#define NSTG 4
#define GM4_SMEM (NSTG * ST4_SZ * 2)   // 108544 bytes

__global__ __launch_bounds__(256) void tc4_gemm(
    const __half* __restrict__ Ahg, const __half* __restrict__ W0,
    const float* __restrict__ bq, const float* __restrict__ bk,
    const float* __restrict__ bv, const float* __restrict__ bo,
    float* __restrict__ out, int job)
{
    const int tid  = threadIdx.x;
    const int lane = tid & 31;
    const int wid  = tid >> 5;
    const int wm   = (wid >> 2) * 64;
    const int wn   = (wid & 3) * 64;
    const int bm   = blockIdx.y * 128;
    const int bn   = blockIdx.x * 256;

    int region, bnl;
    if (job == 1) { region = bn >> 11; bnl = bn & 2047; }
    else          { region = 3;        bnl = bn; }
    const __half* Bhg = W0 + (size_t)region * WSZ;
    const float* bias = (job == 0) ? bo : (region == 0) ? bq
                        : (region == 1) ? bk : bv;

    auto load_stage = [&](int s, int k0) {
        __half* S = gsm + s * ST4_SZ;
#pragma uroll
        for (int c = tid; c < 512; c += 256) {
            int row = c >> 2, ch = (c & 3) * 8;
            size_t aoff = (size_t)(bm + row) * DIMM + k0 + ch;
            cp16(sm_u32(S + SAH + row * 40 + ch), Ahg + aoff);
        }
#pragma unroll
        for (int c = tid; c < 1024; c += 256) {
            int row = c >> 5, nc = (c & 31) * 8;
            size_t boff = (size_t)(k0 + row) * DIMM + bnl + nc;
            cp16(sm_u32(S + SBH + row * 264 + nc), Bhg + boff);
        }
    };

    float acc[4][8][4];
#pragma unroll
    for (int mi = 0; mi < 4; mi++)
#pragma unroll
        for (int ni = 0; ni < 8; ni++)
#pragma unroll
            for (int e = 0; e < 4; e++) acc[mi][ni][e] = 0.0f;

    const int NT = DIMM / 32;   // 64
    load_stage(0, 0);  asm volatile("cp.async.commit_group;" ::: "memory");
    load_stage(1, 32); asm volatile("cp.async.commit_group;" ::: "memory");
    load_stage(2, 64); asm volatile("cp.async.commit_group;" ::: "memory");

    for (int it = 0; it < NT; it++) {
        asm volatile("cp.async.wait_group 2;" ::: "memory");
        __syncthreads();
        if (it + 3 < NT) load_stage((it + 3) & 3, (it + 3) * 32);
        asm volatile("cp.async.commit_group;" ::: "memory");

        const __half* S = gsm + (it & 3) * ST4_SZ;
#pragma unroll
        for (int ks = 0; ks < 2; ks++) {
            uint32_t ah[4][4];
            const int arow = lane & 15;
            const int acol = ks * 16 + (lane >> 4) * 8;
#pragma unroll
            for (int mi = 0; mi < 4; mi++) {
                const __half* pa = S + SAH + (wm + mi * 16 + arow) * 40 + acol;
                ldsm_x4(ah[mi], sm_u32(pa));
            }
            const int brow = ks * 16 + (lane & 15);
#pragma unroll
            for (int half = 0; half < 2; half++) {
                uint32_t bh[2][4];
#pragma unroll
                for (int np = 0; np < 2; np++) {
                    int bcol = wn + (half * 2 + np) * 16 + (lane >> 4) * 8;
                    ldsm_x4t(bh[np], sm_u32(S + SBH + brow * 264 + bcol));
                }
#pragma unroll
                for (int mi = 0; mi < 4; mi++) {
#pragma unroll
                    for (int n4 = 0; n4 < 4; n4++) {
                        mma_f16(acc[mi][half * 4 + n4], ah[mi],
                                bh[n4 >> 1][(n4 & 1) * 2],
                                bh[n4 >> 1][(n4 & 1) * 2 + 1]);
                    }
                }
            }
        }
        __syncthreads();
    }

    // ---- epilogue ----
    __half* Dh = (region == 0) ? g_Qh : (region == 1) ? g_Kh : g_Vh;
    const float QS = 1.4426950408889634f / 128.0f;

#pragma unroll
    for (int mi = 0; mi < 4; mi++) {
#pragma unroll
        for (int ni = 0; ni < 8; ni++) {
            int row0 = bm + wm + mi * 16 + (lane >> 2);
            int colL = bnl + wn + ni * 8 + (lane & 3) * 2;
            float2 bb = *(const float2*)(bias + colL);
            float f0 = acc[mi][ni][0] + bb.x, f1 = acc[mi][ni][1] + bb.y;
            float f2 = acc[mi][ni][2] + bb.x, f3 = acc[mi][ni][3] + bb.y;
            if (job == 0) {
                *(float2*)(out + (size_t)row0 * DIMM + colL)       = make_float2(f0, f1);
                *(float2*)(out + (size_t)(row0 + 8) * DIMM + colL) = make_float2(f2, f3);
            } else {
                if (region <= 1) {   // rope for Q and K
                    int i = (colL & 127) >> 1;
                    float2 cs0 = g_rt[(row0 & (SEQ - 1)) * 64 + i];
                    float2 cs1 = g_rt[((row0 + 8) & (SEQ - 1)) * 64 + i];
                    float t0 = f0 * cs0.x - f1 * cs0.y;
                    float t1 = f1 * cs0.x + f0 * cs0.y;
                    float t2 = f2 * cs1.x - f3 * cs1.y;
                    float t3 = f3 * cs1.x + f2 * cs1.y;
                    if (region == 0) { t0 *= QS; t1 *= QS; t2 *= QS; t3 *= QS; }
                    f0 = t0; f1 = t1; f2 = t2; f3 = t3;
                }
                if (region == 0) {   // Q: hi/lo split
                    uint32_t h0, l0, h1, l1;
                    split2h(f0, f1, h0, l0);
                    split2h(f2, f3, h1, l1);
                    *(uint32_t*)(g_Qh + (size_t)row0 * DIMM + colL)       = h0;
                    *(uint32_t*)(g_Ql + (size_t)row0 * DIMM + colL)       = l0;
                    *(uint32_t*)(g_Qh + (size_t)(row0 + 8) * DIMM + colL) = h1;
                    *(uint32_t*)(g_Ql + (size_t)(row0 + 8) * DIMM + colL) = l1;
                } else {             // K, V: fp16 only
                    *(uint32_t*)(Dh + (size_t)row0 * DIMM + colL)       = packh2(f0, f1);
                    *(uint32_t*)(Dh + (size_t)(row0 + 8) * DIMM + colL) = packh2(f2, f3);
                }
            }
        }
    }
}

// ---------------------------------------------------------------------------
// fp16x2 flash attention: S = (Qh+Ql) K^T (2 mma), O = (Ph+Pl) V (2 mma).
// BR=128 (8 warps x 16 rows), BC=64, d=128, 256 threads.
// smem: Qh[0:32K) Ql[32K:64K) + 2 stages of {K 16K, V 16K} = 128KB total.
// Epilogue writes fp16 O (hi only) for the O projection.
// ---------------------------------------------------------------------------
#define FQH 0u
#define FQL 32768u
#define FST(s) (65536u + (uint32_t)(s) * 32768u)
#define FLASH_SMEM 131072

__device__ __forceinline__ uint32_t fswz(uint32_t row, uint32_t colbyte) {
    uint32_t off = row * 256u + colbyte;
    return off ^ ((row & 7u) << 4);
}

__device__ __forceinline__ void flash_load_kv(
    uint32_t sb, int stage, size_t kb,
    const __half* __restrict__ Kh_, const __half* __restrict__ Vh_, int tid)
{
    uint32_t base = sb + FST(stage);
#pragma unroll
    for (int c = tid; c < 1024; c += 256) {
        uint32_t row = c >> 4, ch = c & 15;
        uint32_t d = fswz(row, ch * 16);
        size_t so = kb + (size_t)row * DIMM + ch * 8;
        cp16(base + d,          Kh_ + so);
        cp16(base + 16384u + d, Vh_ + so);
    }
}

__global__ __launch_bounds__(256) void flash_tc(
    const __half* __restrict__ Qh_, const __half* __restrict__ Ql_,
    const __half* __restrict__ Kh_, const __half* __restrict__ Vh_,
    __half* __restrict__ Ah)
{
    const uint32_t sb = sm_u32(gsm);
    const int tid  = threadIdx.x;
    const int lane = tid & 31;
    const int wid  = tid >> 5;
    const int wr   = wid * 16;
    const int bh   = blockIdx.y;
    const int b    = bh >> 4;
    const int h    = bh & 15;
    const int q0   = blockIdx.x * 128;

    const size_t qg = (size_t)(b * SEQ + q0) * DIMM + h * HDIM;
    const size_t kg0 = (size_t)(b * SEQ) * DIMM + h * HDIM;

#pragma unroll
    for (int c = tid; c < 2048; c += 256) {
        uint32_t row = c >> 4, ch = c & 15;
        uint32_t d = fswz(row, ch * 16);
        size_t so = qg + (size_t)row * DIMM + ch * 8;
        cp16(sb + FQH + d, Qh_ + so);
        cp16(sb + FQL + d, Ql_ + so);
    }
    flash_load_kv(sb, 0, kg0, Kh_, Vh_, tid);
    asm volatile("cp.async.commit_group;" ::: "memory");

    float acc_o[16][4];
#pragma unroll
    for (int ni = 0; ni < 16; ni++)
#pragma unroll
        for (int e = 0; e < 4; e++) acc_o[ni][e] = 0.0f;
    float m_a = -INFINITY, m_b = -INFINITY, l_a = 0.0f, l_b = 0.0f;

    const uint32_t arow = (uint32_t)(wr + (lane & 15));
    const uint32_t chalf = (uint32_t)((lane >> 4) * 16);

    for (int kt = 0; kt < SEQ / 64; kt++) {
        asm volatile("cp.async.wait_group 0;" ::: "memory");
        __syncthreads();
        if (kt + 1 < SEQ / 64) {
            flash_load_kv(sb, (kt + 1) & 1, kg0 + (size_t)(kt + 1) * 64 * DIMM,
                          Kh_, Vh_, tid);
            asm volatile("cp.async.commit_group;" ::: "memory");
        }
        const uint32_t kbase = sb + FST(kt & 1);

        // ---- S = Q K^T (2 mma) ----
        float s[8][4];
#pragma unroll
        for (int j = 0; j < 8; j++)
#pragma unroll
            for (int e = 0; e < 4; e++) s[j][e] = 0.0f;

#pragma unroll
        for (int kc = 0; kc < 8; kc++) {
            uint32_t cb = (uint32_t)kc * 32 + chalf;
            uint32_t aq[4], aql[4];
            ldsm_x4(aq,  sb + FQH + fswz(arow, cb));
            ldsm_x4(aql, sb + FQL + fswz(arow, cb));
#pragma unroll
            for (int g = 0; g < 4; g++) {
                uint32_t krow = (uint32_t)(g * 16 + (lane & 15));
                uint32_t kh4[4];
                ldsm_x4(kh4, kbase + fswz(krow, cb));
                mma_f16(s[2 * g],     aq,  kh4[0], kh4[2]);
                mma_f16(s[2 * g],     aql, kh4[0], kh4[2]);
                mma_f16(s[2 * g + 1], aq,  kh4[1], kh4[3]);
                mma_f16(s[2 * g + 1], aql, kh4[1], kh4[3]);
            }
        }

        // ---- online softmax ----
        float mxa = -INFINITY, mxb = -INFINITY;
#pragma unroll
        for (int j = 0; j < 8; j++) {
            mxa = fmaxf(mxa, fmaxf(s[j][0], s[j][1]));
            mxb = fmaxf(mxb, fmaxf(s[j][2], s[j][3]));
        }
        mxa = fmaxf(mxa, __shfl_xor_sync(0xffffffffu, mxa, 1));
        mxa = fmaxf(mxa, __shfl_xor_sync(0xffffffffu, mxa, 2));
        mxb = fmaxf(mxb, __shfl_xor_sync(0xffffffffu, mxb, 1));
        mxb = fmaxf(mxb, __shfl_xor_sync(0xffffffffu, mxb, 2));

        float mna = fmaxf(m_a, mxa), mnb = fmaxf(m_b, mxb);
        float ca = fexp2(m_a - mna), cb2 = fexp2(m_b - mnb);
        m_a = mna; m_b = mnb;

        float sa = 0.0f, sbv = 0.0f;
        uint32_t ph[8][2], pl[8][2];
#pragma unroll
        for (int j = 0; j < 8; j++) {
            float p0 = fexp2(s[j][0] - mna);
            float p1 = fexp2(s[j][1] - mna);
            float p2 = fexp2(s[j][2] - mnb);
            float p3 = fexp2(s[j][3] - mnb);
            sa  += p0 + p1;
            sbv += p2 + p3;
            split2h(p0, p1, ph[j][0], pl[j][0]);
            split2h(p2, p3, ph[j][1], pl[j][1]);
        }
        sa  += __shfl_xor_sync(0xffffffffu, sa, 1);
        sa  += __shfl_xor_sync(0xffffffffu, sa, 2);
        sbv += __shfl_xor_sync(0xffffffffu, sbv, 1);
        sbv += __shfl_xor_sync(0xffffffffu, sbv, 2);
        l_a = l_a * ca + sa;
        l_b = l_b * cb2 + sbv;

#pragma unroll
        for (int ni = 0; ni < 16; ni++) {
            acc_o[ni][0] *= ca;  acc_o[ni][1] *= ca;
            acc_o[ni][2] *= cb2; acc_o[ni][3] *= cb2;
        }

        // ---- O += P V (2 mma) ----
        const uint32_t vb = kbase + 16384u;
#pragma unroll
        for (int kc2 = 0; kc2 < 4; kc2++) {
            uint32_t aPh[4] = {ph[2 * kc2][0], ph[2 * kc2][1],
                               ph[2 * kc2 + 1][0], ph[2 * kc2 + 1][1]};
            uint32_t aPl[4] = {pl[2 * kc2][0], pl[2 * kc2][1],
                               pl[2 * kc2 + 1][0], pl[2 * kc2 + 1][1]};
            uint32_t vrow = (uint32_t)(kc2 * 16 + (lane & 15));
#pragma unroll
            for (int nd = 0; nd < 8; nd++) {
                uint32_t cb = (uint32_t)nd * 32 + chalf;
                uint32_t vh4[4];
                ldsm_x4t(vh4, vb + fswz(vrow, cb));
                mma_f16(acc_o[2 * nd],     aPh, vh4[0], vh4[1]);
                mma_f16(acc_o[2 * nd],     aPl, vh4[0], vh4[1]);
                mma_f16(acc_o[2 * nd + 1], aPh, vh4[2], vh4[3]);
                mma_f16(acc_o[2 * nd + 1], aPl, vh4[2], vh4[3]);
            }
        }
    }

    // ---- epilogue: normalize, fp16 store ----
    float inva = __fdividef(1.0f, l_a);
    float invb = __fdividef(1.0f, l_b);
    int gr = lane >> 2, c2 = (lane & 3) * 2;
    size_t oa = (size_t)(b * SEQ + q0 + wr + gr) * DIMM + h * HDIM;
    size_t ob = oa + (size_t)8 * DIMM;
#pragma unroll
    for (int ni = 0; ni < 16; ni++) {
        int col = ni * 8 + c2;
        *(uint32_t*)&Ah[oa + col] = packh2(acc_o[ni][0] * inva, acc_o[ni][1] * inva);
        *(uint32_t*)&Ah[ob + col] = packh2(acc_o[ni][2] * invb, acc_o[ni][3] * invb);
    }
}

// ---------------------------------------------------------------------------
extern "C" void kernel_launch(void* const* d_in, const int* in_sizes, int n_in,
                              void* d_out, int out_size)
{
    const float* x  = (const float*)d_in[0];
    const float* Wq = (const float*)d_in[1];
    const float* bq = (const float*)d_in[2];
    const float* Wk = (const float*)d_in[3];
    const float* bk = (const float*)d_in[4];
    const float* Wv = (const float*)d_in[5];
    const float* bv = (const float*)d_in[6];
    const float* Wo = (const float*)d_in[7];
    const float* bo = (const float*)d_in[8];
    float* out = (float*)d_out;

    __half *x16, *w, *qh, *ql, *kh, *vh, *ah;
    cudaGetSymbolAddress((void**)&x16, g_x16);
    cudaGetSymbolAddress((void**)&w,   g_W);
    cudaGetSymbolAddress((void**)&qh,  g_Qh);
    cudaGetSymbolAddress((void**)&ql,  g_Ql);
    cudaGetSymbolAddress((void**)&kh,  g_Kh);
    cudaGetSymbolAddress((void**)&vh,  g_Vh);
    cudaGetSymbolAddress((void**)&ah,  g_Ah);

    cudaFuncSetAttribute(tc4_gemm,
                         cudaFuncAttributeMaxDynamicSharedMemorySize, GM4_SMEM);
    cudaFuncSetAttribute(flash_tc,
                         cudaFuncAttributeMaxDynamicSharedMemorySize, FLASH_SMEM);

    const int NX = MTOK * DIMM;
    const int NW = DIMM * DIMM;

    convert_kernel<<<NX / 4 / 256, 256>>>(x, x16, NX);
    convert_kernel<<<NW / 4 / 256, 256>>>(Wq, w + 0 * WSZ, NW);
    convert_kernel<<<NW / 4 / 256, 256>>>(Wk, w + 1 * WSZ, NW);
    convert_kernel<<<NW / 4 / 256, 256>>>(Wv, w + 2 * WSZ, NW);
    convert_kernel<<<NW / 4 / 256, 256>>>(Wo, w + 3 * WSZ, NW);
    rope_table_kernel<<<(SEQ * 64) / 256, 256>>>();

    // Fused Q/K/V projection + bias + RoPE + fp16 pack
    tc4_gemm<<<dim3(3 * DIMM / 256, MTOK / 128), 256, GM4_SMEM>>>(
        x16, w, bq, bk, bv, bo, nullptr, 1);

    flash_tc<<<dim3(SEQ / 128, BATCH * NHEAD), 256, FLASH_SMEM>>>(
        qh, ql, kh, vh, ah);

    // Output projection (fp32 + bias)
    tc4_gemm<<<dim3(DIMM / 256, MTOK / 128), 256, GM4_SMEM>>>(
        ah, w, bq, bk, bv, bo, out, 0);
}

// round 14
// speedup vs baseline: 1.7492x; 1.7492x over previous
#include <cuda_runtime.h>
#include <cuda_fp16.h>
#include <math.h>
#include <stdint.h>

#define DIMM   2048
#define NHEAD  16
#define HDIM   128
#define SEQ    2048
#define BATCH  2
#define MTOK   (BATCH*SEQ)   // 4096 tokens
#define WSZ    ((size_t)DIMM * DIMM)

// ---------------------------------------------------------------------------
// Device-global scratch (no allocation allowed)
// ---------------------------------------------------------------------------
__device__ __half g_x16[(size_t)MTOK * DIMM];   // x, fp16
__device__ __half g_W[4][WSZ];                  // weights, fp16
__device__ __half g_Qh[(size_t)MTOK * DIMM];
__device__ __half g_Ql[(size_t)MTOK * DIMM];
__device__ __half g_Kh[(size_t)MTOK * DIMM];
__device__ __half g_Vh[(size_t)MTOK * DIMM];
__device__ __half g_Ah[(size_t)MTOK * DIMM];

__device__ float2 g_rt[SEQ * 64];   // RoPE cos/sin table

// ---------------------------------------------------------------------------
// PTX helpers
// ---------------------------------------------------------------------------
__device__ __forceinline__ uint32_t sm_u32(const void* p) {
    return (uint32_t)__cvta_generic_to_shared(p);
}
__device__ __forceinline__ void cp16(uint32_t dst, const void* src) {
    asm volatile("cp.async.cg.shared.global [%0], [%1], 16;" :: "r"(dst), "l"(src) : "memory");
}
__device__ __forceinline__ void ldsm_x4(uint32_t* r, uint32_t a) {
    asm volatile("ldmatrix.sync.aligned.m8n8.x4.shared.b16 {%0,%1,%2,%3}, [%4];"
                 : "=r"(r[0]), "=r"(r[1]), "=r"(r[2]), "=r"(r[3]) : "r"(a));
}
__device__ __forceinline__ void ldsm_x4t(uint32_t* r, uint32_t a) {
    asm volatile("ldmatrix.sync.aligned.m8n8.x4.trans.shared.b16 {%0,%1,%2,%3}, [%4];"
                 : "=r"(r[0]), "=r"(r[1]), "=r"(r[2]), "=r"(r[3]) : "r"(a));
}
__device__ __forceinline__ void mma_f16(float* c, const uint32_t* a,
                                        uint32_t b0, uint32_t b1) {
    asm volatile(
        "mma.sync.aligned.m16n8k16.row.col.f32.f16.f16.f32 "
        "{%0,%1,%2,%3}, {%4,%5,%6,%7}, {%8,%9}, {%0,%1,%2,%3};"
        : "+f"(c[0]), "+f"(c[1]), "+f"(c[2]), "+f"(c[3])
        : "r"(a[0]), "r"(a[1]), "r"(a[2]), "r"(a[3]), "r"(b0), "r"(b1));
}
__device__ __forceinline__ float fexp2(float x) {
    float y;
    asm("ex2.approx.ftz.f32 %0, %1;" : "=f"(y) : "f"(x));
    return y;
}
__device__ __forceinline__ uint32_t packh2(float f0, float f1) {
    __half2 h = __floats2half2_rn(f0, f1);
    return *(uint32_t*)&h;
}
__device__ __forceinline__ void split2h(float f0, float f1,
                                        uint32_t& hi, uint32_t& lo) {
    __half2 h = __floats2half2_rn(f0, f1);
    float2 fb = __half22float2(h);
    __half2 l = __floats2half2_rn(f0 - fb.x, f1 - fb.y);
    hi = *(uint32_t*)&h;
    lo = *(uint32_t*)&l;
}

extern __shared__ __half gsm[];

// ---------------------------------------------------------------------------
// Convert fp32 -> fp16
// ---------------------------------------------------------------------------
__global__ __launch_bounds__(256) void convert_kernel(
    const float* __restrict__ src, __half* __restrict__ dst, int n)
{
    int i = (blockIdx.x * blockDim.x + threadIdx.x) * 4;
    if (i >= n) return;
    float4 v = *(const float4*)(src + i);
    *(uint32_t*)(dst + i)     = packh2(v.x, v.y);
    *(uint32_t*)(dst + i + 2) = packh2(v.z, v.w);
}

// ---------------------------------------------------------------------------
// RoPE table (double precision)
// ---------------------------------------------------------------------------
__global__ __launch_bounds__(256) void rope_table_kernel()
{
    int idx = blockIdx.x * blockDim.x + threadIdx.x;
    if (idx >= SEQ * 64) return;
    int pos = idx >> 6, i = idx & 63;
    double invf = pow(10000.0, -(double)i / 64.0);
    double sd, cd;
    sincos((double)pos * invf, &sd, &cd);
    g_rt[idx] = make_float2((float)cd, (float)sd);
}

// ---------------------------------------------------------------------------
// fp16 GEMM, BK=64: CTA 128x256, 8 warps of 64x64, 4-stage cp.async (52KB/stg).
// A fp16 [M,K], B = W fp16 [K,N] row-major (ldsm trans).
// job==1 (QKV fused, blockIdx.x selects region):
//   region 0 (Q): bias + rope + qscale + fp16 hi/lo split
//   region 1 (K): bias + rope + fp16 ; region 2 (V): bias + fp16
// job==0 (O): bias + fp32 store.
// ---------------------------------------------------------------------------
#define AST5 72                    // A row stride (halfs): 64 + 8 pad
#define SBH5 (128*AST5)            // 9216 halfs
#define BST5 264                   // B row stride (halfs): 256 + 8 pad
#define ST5_SZ (SBH5 + 64*BST5)    // 26112 halfs per stage (52224 B)
#define NSTG5 4
#define GM5_SMEM (NSTG5 * ST5_SZ * 2)   // 208896 bytes

__global__ __launch_bounds__(256) void tc5_gemm(
    const __half* __restrict__ Ahg, const __half* __restrict__ W0,
    const float* __restrict__ bq, const float* __restrict__ bk,
    const float* __restrict__ bv, const float* __restrict__ bo,
    float* __restrict__ out, int job)
{
    const int tid  = threadIdx.x;
    const int lane = tid & 31;
    const int wid  = tid >> 5;
    const int wm   = (wid >> 2) * 64;
    const int wn   = (wid & 3) * 64;
    const int bm   = blockIdx.y * 128;
    const int bn   = blockIdx.x * 256;

    int region, bnl;
    if (job == 1) { region = bn >> 11; bnl = bn & 2047; }
    else          { region = 3;        bnl = bn; }
    const __half* Bhg = W0 + (size_t)region * WSZ;
    const float* bias = (job == 0) ? bo : (region == 0) ? bq
                        : (region == 1) ? bk : bv;

    auto load_stage = [&](int s, int k0) {
        __half* S = gsm + s * ST5_SZ;
#pragma unroll
        for (int c = tid; c < 1024; c += 256) {
            int row = c >> 3, ch = (c & 7) * 8;
            size_t aoff = (size_t)(bm + row) * DIMM + k0 + ch;
            cp16(sm_u32(S + row * AST5 + ch), Ahg + aoff);
        }
#pragma unroll
        for (int c = tid; c < 2048; c += 256) {
            int row = c >> 5, nc = (c & 31) * 8;
            size_t boff = (size_t)(k0 + row) * DIMM + bnl + nc;
            cp16(sm_u32(S + SBH5 + row * BST5 + nc), Bhg + boff);
        }
    };

    float acc[4][8][4];
#pragma unroll
    for (int mi = 0; mi < 4; mi++)
#pragma unroll
        for (int ni = 0; ni < 8; ni++)
#pragma unroll
            for (int e = 0; e < 4; e++) acc[mi][ni][e] = 0.0f;

    const int NT = DIMM / 64;   // 32
    load_stage(0, 0);   asm volatile("cp.async.commit_group;" ::: "memory");
    load_stage(1, 64);  asm volatile("cp.async.commit_group;" ::: "memory");
    load_stage(2, 128); asm volatile("cp.async.commit_group;" ::: "memory");

    for (int it = 0; it < NT; it++) {
        asm volatile("cp.async.wait_group 2;" ::: "memory");
        __syncthreads();
        if (it + 3 < NT) load_stage((it + 3) & 3, (it + 3) * 64);
        asm volatile("cp.async.commit_group;" ::: "memory");

        const __half* S = gsm + (it & 3) * ST5_SZ;
#pragma unroll
        for (int ks = 0; ks < 4; ks++) {
            uint32_t ah[4][4];
            const int arow = lane & 15;
            const int acol = ks * 16 + (lane >> 4) * 8;
#pragma unroll
            for (int mi = 0; mi < 4; mi++) {
                const __half* pa = S + (wm + mi * 16 + arow) * AST5 + acol;
                ldsm_x4(ah[mi], sm_u32(pa));
            }
            const int brow = ks * 16 + (lane & 15);
#pragma unroll
            for (int half = 0; half < 2; half++) {
                uint32_t bh[2][4];
#pragma unroll
                for (int np = 0; np < 2; np++) {
                    int bcol = wn + (half * 2 + np) * 16 + (lane >> 4) * 8;
                    ldsm_x4t(bh[np], sm_u32(S + SBH5 + brow * BST5 + bcol));
                }
#pragma unroll
                for (int mi = 0; mi < 4; mi++) {
#pragma unroll
                    for (int n4 = 0; n4 < 4; n4++) {
                        mma_f16(acc[mi][half * 4 + n4], ah[mi],
                                bh[n4 >> 1][(n4 & 1) * 2],
                                bh[n4 >> 1][(n4 & 1) * 2 + 1]);
                    }
                }
            }
        }
        __syncthreads();
    }

    // ---- epilogue ----
    __half* Dh = (region == 0) ? g_Qh : (region == 1) ? g_Kh : g_Vh;
    const float QS = 1.4426950408889634f / 128.0f;

#pragma unroll
    for (int mi = 0; mi < 4; mi++) {
#pragma unroll
        for (int ni = 0; ni < 8; ni++) {
            int row0 = bm + wm + mi * 16 + (lane >> 2);
            int colL = bnl + wn + ni * 8 + (lane & 3) * 2;
            float2 bb = *(const float2*)(bias + colL);
            float f0 = acc[mi][ni][0] + bb.x, f1 = acc[mi][ni][1] + bb.y;
            float f2 = acc[mi][ni][2] + bb.x, f3 = acc[mi][ni][3] + bb.y;
            if (job == 0) {
                *(float2*)(out + (size_t)row0 * DIMM + colL)       = make_float2(f0, f1);
                *(float2*)(out + (size_t)(row0 + 8) * DIMM + colL) = make_float2(f2, f3);
            } else {
                if (region <= 1) {   // rope for Q and K
                    int i = (colL & 127) >> 1;
                    float2 cs0 = g_rt[(row0 & (SEQ - 1)) * 64 + i];
                    float2 cs1 = g_rt[((row0 + 8) & (SEQ - 1)) * 64 + i];
                    float t0 = f0 * cs0.x - f1 * cs0.y;
                    float t1 = f1 * cs0.x + f0 * cs0.y;
                    float t2 = f2 * cs1.x - f3 * cs1.y;
                    float t3 = f3 * cs1.x + f2 * cs1.y;
                    if (region == 0) { t0 *= QS; t1 *= QS; t2 *= QS; t3 *= QS; }
                    f0 = t0; f1 = t1; f2 = t2; f3 = t3;
                }
                if (region == 0) {   // Q: hi/lo split
                    uint32_t h0, l0, h1, l1;
                    split2h(f0, f1, h0, l0);
                    split2h(f2, f3, h1, l1);
                    *(uint32_t*)(g_Qh + (size_t)row0 * DIMM + colL)       = h0;
                    *(uint32_t*)(g_Ql + (size_t)row0 * DIMM + colL)       = l0;
                    *(uint32_t*)(g_Qh + (size_t)(row0 + 8) * DIMM + colL) = h1;
                    *(uint32_t*)(g_Ql + (size_t)(row0 + 8) * DIMM + colL) = l1;
                } else {             // K, V: fp16 only
                    *(uint32_t*)(Dh + (size_t)row0 * DIMM + colL)       = packh2(f0, f1);
                    *(uint32_t*)(Dh + (size_t)(row0 + 8) * DIMM + colL) = packh2(f2, f3);
                }
            }
        }
    }
}

// ---------------------------------------------------------------------------
// fp16 flash attention: S = (Qh+Ql) K^T (2 mma), O = P V (1 mma, P fp16).
// BR=128 (8 warps x 16 rows), BC=64, d=128, 256 threads.
// smem: Qh[0:32K) Ql[32K:64K) + 2 stages of {K 16K, V 16K} = 128KB total.
// ---------------------------------------------------------------------------
#define FQH 0u
#define FQL 32768u
#define FST(s) (65536u + (uint32_t)(s) * 32768u)
#define FLASH_SMEM 131072

__device__ __forceinline__ uint32_t fswz(uint32_t row, uint32_t colbyte) {
    uint32_t off = row * 256u + colbyte;
    return off ^ ((row & 7u) << 4);
}

__device__ __forceinline__ void flash_load_kv(
    uint32_t sb, int stage, size_t kb,
    const __half* __restrict__ Kh_, const __half* __restrict__ Vh_, int tid)
{
    uint32_t base = sb + FST(stage);
#pragma unroll
    for (int c = tid; c < 1024; c += 256) {
        uint32_t row = c >> 4, ch = c & 15;
        uint32_t d = fswz(row, ch * 16);
        size_t so = kb + (size_t)row * DIMM + ch * 8;
        cp16(base + d,          Kh_ + so);
        cp16(base + 16384u + d, Vh_ + so);
    }
}

__global__ __launch_bounds__(256) void flash_tc(
    const __half* __restrict__ Qh_, const __half* __restrict__ Ql_,
    const __half* __restrict__ Kh_, const __half* __restrict__ Vh_,
    __half* __restrict__ Ah)
{
    const uint32_t sb = sm_u32(gsm);
    const int tid  = threadIdx.x;
    const int lane = tid & 31;
    const int wid  = tid >> 5;
    const int wr   = wid * 16;
    const int bh   = blockIdx.y;
    const int b    = bh >> 4;
    const int h    = bh & 15;
    const int q0   = blockIdx.x * 128;

    const size_t qg = (size_t)(b * SEQ + q0) * DIMM + h * HDIM;
    const size_t kg0 = (size_t)(b * SEQ) * DIMM + h * HDIM;

#pragma unroll
    for (int c = tid; c < 2048; c += 256) {
        uint32_t row = c >> 4, ch = c & 15;
        uint32_t d = fswz(row, ch * 16);
        size_t so = qg + (size_t)row * DIMM + ch * 8;
        cp16(sb + FQH + d, Qh_ + so);
        cp16(sb + FQL + d, Ql_ + so);
    }
    flash_load_kv(sb, 0, kg0, Kh_, Vh_, tid);
    asm volatile("cp.async.commit_group;" ::: "memory");

    float acc_o[16][4];
#pragma unroll
    for (int ni = 0; ni < 16; ni++)
#pragma unroll
        for (int e = 0; e < 4; e++) acc_o[ni][e] = 0.0f;
    float m_a = -INFINITY, m_b = -INFINITY, l_a = 0.0f, l_b = 0.0f;

    const uint32_t arow = (uint32_t)(wr + (lane & 15));
    const uint32_t chalf = (uint32_t)((lane >> 4) * 16);

    for (int kt = 0; kt < SEQ / 64; kt++) {
        asm volatile("cp.async.wait_group 0;" ::: "memory");
        __syncthreads();
        if (kt + 1 < SEQ / 64) {
            flash_load_kv(sb, (kt + 1) & 1, kg0 + (size_t)(kt + 1) * 64 * DIMM,
                          Kh_, Vh_, tid);
            asm volatile("cp.async.commit_group;" ::: "memory");
        }
        const uint32_t kbase = sb + FST(kt & 1);

        // ---- S = Q K^T (2 mma) ----
        float s[8][4];
#pragma unroll
        for (int j = 0; j < 8; j++)
#pragma unroll
            for (int e = 0; e < 4; e++) s[j][e] = 0.0f;

#pragma unroll
        for (int kc = 0; kc < 8; kc++) {
            uint32_t cb = (uint32_t)kc * 32 + chalf;
            uint32_t aq[4], aql[4];
            ldsm_x4(aq,  sb + FQH + fswz(arow, cb));
            ldsm_x4(aql, sb + FQL + fswz(arow, cb));
#pragma unroll
            for (int g = 0; g < 4; g++) {
                uint32_t krow = (uint32_t)(g * 16 + (lane & 15));
                uint32_t kh4[4];
                ldsm_x4(kh4, kbase + fswz(krow, cb));
                mma_f16(s[2 * g],     aq,  kh4[0], kh4[2]);
                mma_f16(s[2 * g],     aql, kh4[0], kh4[2]);
                mma_f16(s[2 * g + 1], aq,  kh4[1], kh4[3]);
                mma_f16(s[2 * g + 1], aql, kh4[1], kh4[3]);
            }
        }

        // ---- online softmax ----
        float mxa = -INFINITY, mxb = -INFINITY;
#pragma unroll
        for (int j = 0; j < 8; j++) {
            mxa = fmaxf(mxa, fmaxf(s[j][0], s[j][1]));
            mxb = fmaxf(mxb, fmaxf(s[j][2], s[j][3]));
        }
        mxa = fmaxf(mxa, __shfl_xor_sync(0xffffffffu, mxa, 1));
        mxa = fmaxf(mxa, __shfl_xor_sync(0xffffffffu, mxa, 2));
        mxb = fmaxf(mxb, __shfl_xor_sync(0xffffffffu, mxb, 1));
        mxb = fmaxf(mxb, __shfl_xor_sync(0xffffffffu, mxb, 2));

        float mna = fmaxf(m_a, mxa), mnb = fmaxf(m_b, mxb);
        float ca = fexp2(m_a - mna), cb2 = fexp2(m_b - mnb);
        m_a = mna; m_b = mnb;

        float sa = 0.0f, sbv = 0.0f;
        uint32_t ph[8][2];
#pragma unroll
        for (int j = 0; j < 8; j++) {
            float p0 = fexp2(s[j][0] - mna);
            float p1 = fexp2(s[j][1] - mna);
            float p2 = fexp2(s[j][2] - mnb);
            float p3 = fexp2(s[j][3] - mnb);
            sa  += p0 + p1;
            sbv += p2 + p3;
            ph[j][0] = packh2(p0, p1);
            ph[j][1] = packh2(p2, p3);
        }
        sa  += __shfl_xor_sync(0xffffffffu, sa, 1);
        sa  += __shfl_xor_sync(0xffffffffu, sa, 2);
        sbv += __shfl_xor_sync(0xffffffffu, sbv, 1);
        sbv += __shfl_xor_sync(0xffffffffu, sbv, 2);
        l_a = l_a * ca + sa;
        l_b = l_b * cb2 + sbv;

#pragma unroll
        for (int ni = 0; ni < 16; ni++) {
            acc_o[ni][0] *= ca;  acc_o[ni][1] *= ca;
            acc_o[ni][2] *= cb2; acc_o[ni][3] *= cb2;
        }

        // ---- O += P V (1 mma, P fp16) ----
        const uint32_t vb = kbase + 16384u;
#pragma unroll
        for (int kc2 = 0; kc2 < 4; kc2++) {
            uint32_t aPh[4] = {ph[2 * kc2][0], ph[2 * kc2][1],
                               ph[2 * kc2 + 1][0], ph[2 * kc2 + 1][1]};
            uint32_t vrow = (uint32_t)(kc2 * 16 + (lane & 15));
#pragma unroll
            for (int nd = 0; nd < 8; nd++) {
                uint32_t cb = (uint32_t)nd * 32 + chalf;
                uint32_t vh4[4];
                ldsm_x4t(vh4, vb + fswz(vrow, cb));
                mma_f16(acc_o[2 * nd],     aPh, vh4[0], vh4[1]);
                mma_f16(acc_o[2 * nd + 1], aPh, vh4[2], vh4[3]);
            }
        }
    }

    // ---- epilogue: normalize, fp16 store ----
    float inva = __fdividef(1.0f, l_a);
    float invb = __fdividef(1.0f, l_b);
    int gr = lane >> 2, c2 = (lane & 3) * 2;
    size_t oa = (size_t)(b * SEQ + q0 + wr + gr) * DIMM + h * HDIM;
    size_t ob = oa + (size_t)8 * DIMM;
#pragma unroll
    for (int ni = 0; ni < 16; ni++) {
        int col = ni * 8 + c2;
        *(uint32_t*)&Ah[oa + col] = packh2(acc_o[ni][0] * inva, acc_o[ni][1] * inva);
        *(uint32_t*)&Ah[ob + col] = packh2(acc_o[ni][2] * invb, acc_o[ni][3] * invb);
    }
}

// ---------------------------------------------------------------------------
extern "C" void kernel_launch(void* const* d_in, const int* in_sizes, int n_in,
                              void* d_out, int out_size)
{
    const float* x  = (const float*)d_in[0];
    const float* Wq = (const float*)d_in[1];
    const float* bq = (const float*)d_in[2];
    const float* Wk = (const float*)d_in[3];
    const float* bk = (const float*)d_in[4];
    const float* Wv = (const float*)d_in[5];
    const float* bv = (const float*)d_in[6];
    const float* Wo = (const float*)d_in[7];
    const float* bo = (const float*)d_in[8];
    float* out = (float*)d_out;

    __half *x16, *w, *qh, *ql, *kh, *vh, *ah;
    cudaGetSymbolAddress((void**)&x16, g_x16);
    cudaGetSymbolAddress((void**)&w,   g_W);
    cudaGetSymbolAddress((void**)&qh,  g_Qh);
    cudaGetSymbolAddress((void**)&ql,  g_Ql);
    cudaGetSymbolAddress((void**)&kh,  g_Kh);
    cudaGetSymbolAddress((void**)&vh,  g_Vh);
    cudaGetSymbolAddress((void**)&ah,  g_Ah);

    cudaFuncSetAttribute(tc5_gemm,
                         cudaFuncAttributeMaxDynamicSharedMemorySize, GM5_SMEM);
    cudaFuncSetAttribute(flash_tc,
                         cudaFuncAttributeMaxDynamicSharedMemorySize, FLASH_SMEM);

    const int NX = MTOK * DIMM;
    const int NW = DIMM * DIMM;

    convert_kernel<<<NX / 4 / 256, 256>>>(x, x16, NX);
    convert_kernel<<<NW / 4 / 256, 256>>>(Wq, w + 0 * WSZ, NW);
    convert_kernel<<<NW / 4 / 256, 256>>>(Wk, w + 1 * WSZ, NW);
    convert_kernel<<<NW / 4 / 256, 256>>>(Wv, w + 2 * WSZ, NW);
    convert_kernel<<<NW / 4 / 256, 256>>>(Wo, w + 3 * WSZ, NW);
    rope_table_kernel<<<(SEQ * 64) / 256, 256>>>();

    // Fused Q/K/V projection + bias + RoPE + fp16 pack
    tc5_gemm<<<dim3(3 * DIMM / 256, MTOK / 128), 256, GM5_SMEM>>>(
        x16, w, bq, bk, bv, bo, nullptr, 1);

    flash_tc<<<dim3(SEQ / 128, BATCH * NHEAD), 256, FLASH_SMEM>>>(
        qh, ql, kh, vh, ah);

    // Output projection (fp32 + bias)
    tc5_gemm<<<dim3(DIMM / 256, MTOK / 128), 256, GM5_SMEM>>>(
        ah, w, bq, bk, bv, bo, out, 0);
}

// round 17
// speedup vs baseline: 1.9405x; 1.1094x over previous
#include <cuda_runtime.h>
#include <cuda_fp16.h>
#include <math.h>
#include <stdint.h>

#define DIMM   2048
#define NHEAD  16
#define HDIM   128
#define SEQ    2048
#define BATCH  2
#define MTOK   (BATCH*SEQ)   // 4096 tokens
#define WSZ    ((size_t)DIMM * DIMM)

// ---------------------------------------------------------------------------
// Device-global scratch (no allocation allowed)
// ---------------------------------------------------------------------------
__device__ __half g_x16[(size_t)MTOK * DIMM];   // x, fp16
__device__ __half g_W[4][WSZ];                  // weights, fp16
__device__ __half g_Qh[(size_t)MTOK * DIMM];    // fp16 (rope+scale applied)
__device__ __half g_Kh[(size_t)MTOK * DIMM];    // fp16 (rope applied)
__device__ __half g_Vh[(size_t)MTOK * DIMM];    // fp16
__device__ __half g_Ah[(size_t)MTOK * DIMM];    // flash out, fp16

__device__ float2 g_rt[SEQ * 64];   // RoPE cos/sin table

// ---------------------------------------------------------------------------
// PTX helpers
// ---------------------------------------------------------------------------
__device__ __forceinline__ uint32_t sm_u32(const void* p) {
    return (uint32_t)__cvta_generic_to_shared(p);
}
__device__ __forceinline__ void cp16(uint32_t dst, const void* src) {
    asm volatile("cp.async.cg.shared.global [%0], [%1], 16;" :: "r"(dst), "l"(src) : "memory");
}
__device__ __forceinline__ void ldsm_x4(uint32_t* r, uint32_t a) {
    asm volatile("ldmatrix.sync.aligned.m8n8.x4.shared.b16 {%0,%1,%2,%3}, [%4];"
                 : "=r"(r[0]), "=r"(r[1]), "=r"(r[2]), "=r"(r[3]) : "r"(a));
}
__device__ __forceinline__ void ldsm_x4t(uint32_t* r, uint32_t a) {
    asm volatile("ldmatrix.sync.aligned.m8n8.x4.trans.shared.b16 {%0,%1,%2,%3}, [%4];"
                 : "=r"(r[0]), "=r"(r[1]), "=r"(r[2]), "=r"(r[3]) : "r"(a));
}
__device__ __forceinline__ void mma_f16(float* c, const uint32_t* a,
                                        uint32_t b0, uint32_t b1) {
    asm volatile(
        "mma.sync.aligned.m16n8k16.row.col.f32.f16.f16.f32 "
        "{%0,%1,%2,%3}, {%4,%5,%6,%7}, {%8,%9}, {%0,%1,%2,%3};"
        : "+f"(c[0]), "+f"(c[1]), "+f"(c[2]), "+f"(c[3])
        : "r"(a[0]), "r"(a[1]), "r"(a[2]), "r"(a[3]), "r"(b0), "r"(b1));
}
__device__ __forceinline__ float fexp2(float x) {
    float y;
    asm("ex2.approx.ftz.f32 %0, %1;" : "=f"(y) : "f"(x));
    return y;
}
__device__ __forceinline__ uint32_t packh2(float f0, float f1) {
    __half2 h = __floats2half2_rn(f0, f1);
    return *(uint32_t*)&h;
}

extern __shared__ __half gsm[];

// ---------------------------------------------------------------------------
// Convert fp32 -> fp16
// ---------------------------------------------------------------------------
__global__ __launch_bounds__(256) void convert_kernel(
    const float* __restrict__ src, __half* __restrict__ dst, int n)
{
    int i = (blockIdx.x * blockDim.x + threadIdx.x) * 4;
    if (i >= n) return;
    float4 v = *(const float4*)(src + i);
    *(uint32_t*)(dst + i)     = packh2(v.x, v.y);
    *(uint32_t*)(dst + i + 2) = packh2(v.z, v.w);
}

// ---------------------------------------------------------------------------
// RoPE table (double precision)
// ---------------------------------------------------------------------------
__global__ __launch_bounds__(256) void rope_table_kernel()
{
    int idx = blockIdx.x * blockDim.x + threadIdx.x;
    if (idx >= SEQ * 64) return;
    int pos = idx >> 6, i = idx & 63;
    double invf = pow(10000.0, -(double)i / 64.0);
    double sd, cd;
    sincos((double)pos * invf, &sd, &cd);
    g_rt[idx] = make_float2((float)cd, (float)sd);
}

// ---------------------------------------------------------------------------
// fp16 GEMM, BK=64: CTA 128x256, 8 warps of 64x64, 4-stage cp.async (52KB/stg).
// A fp16 [M,K], B = W fp16 [K,N] row-major (ldsm trans).
// job==1 (QKV fused, blockIdx.x selects region):
//   region 0 (Q): bias + rope + qscale -> fp16
//   region 1 (K): bias + rope -> fp16 ; region 2 (V): bias -> fp16
// job==0 (O): bias + fp32 store.
// ---------------------------------------------------------------------------
#define AST5 72                    // A row stride (halfs): 64 + 8 pad
#define SBH5 (128*AST5)            // 9216 halfs
#define BST5 264                   // B row stride (halfs): 256 + 8 pad
#define ST5_SZ (SBH5 + 64*BST5)    // 26112 halfs per stage (52224 B)
#define NSTG5 4
#define GM5_SMEM (NSTG5 * ST5_SZ * 2)   // 208896 bytes

__global__ __launch_bounds__(256) void tc5_gemm(
    const __half* __restrict__ Ahg, const __half* __restrict__ W0,
    const float* __restrict__ bq, const float* __restrict__ bk,
    const float* __restrict__ bv, const float* __restrict__ bo,
    float* __restrict__ out, int job)
{
    const int tid  = threadIdx.x;
    const int lane = tid & 31;
    const int wid  = tid >> 5;
    const int wm   = (wid >> 2) * 64;
    const int wn   = (wid & 3) * 64;
    const int bm   = blockIdx.y * 128;
    const int bn   = blockIdx.x * 256;

    int region, bnl;
    if (job == 1) { region = bn >> 11; bnl = bn & 2047; }
    else          { region = 3;        bnl = bn; }
    const __half* Bhg = W0 + (size_t)region * WSZ;
    const float* bias = (job == 0) ? bo : (region == 0) ? bq
                        : (region == 1) ? bk : bv;

    auto load_stage = [&](int s, int k0) {
        __half* S = gsm + s * ST5_SZ;
#pragma unroll
        for (int c = tid; c < 1024; c += 256) {
            int row = c >> 3, ch = (c & 7) * 8;
            size_t aoff = (size_t)(bm + row) * DIMM + k0 + ch;
            cp16(sm_u32(S + row * AST5 + ch), Ahg + aoff);
        }
#pragma unroll
        for (int c = tid; c < 2048; c += 256) {
            int row = c >> 5, nc = (c & 31) * 8;
            size_t boff = (size_t)(k0 + row) * DIMM + bnl + nc;
            cp16(sm_u32(S + SBH5 + row * BST5 + nc), Bhg + boff);
        }
    };

    float acc[4][8][4];
#pragma unroll
    for (int mi = 0; mi < 4; mi++)
#pragma unroll
        for (int ni = 0; ni < 8; ni++)
#pragma unroll
            for (int e = 0; e < 4; e++) acc[mi][ni][e] = 0.0f;

    const int NT = DIMM / 64;   // 32
    load_stage(0, 0);   asm volatile("cp.async.commit_group;" ::: "memory");
    load_stage(1, 64);  asm volatile("cp.async.commit_group;" ::: "memory");
    load_stage(2, 128); asm volatile("cp.async.commit_group;" ::: "memory");

    for (int it = 0; it < NT; it++) {
        asm volatile("cp.async.wait_group 2;" ::: "memory");
        __syncthreads();
        if (it + 3 < NT) load_stage((it + 3) & 3, (it + 3) * 64);
        asm volatile("cp.async.commit_group;" ::: "memory");

        const __half* S = gsm + (it & 3) * ST5_SZ;
#pragma unroll
        for (int ks = 0; ks < 4; ks++) {
            uint32_t ah[4][4];
            const int arow = lane & 15;
            const int acol = ks * 16 + (lane >> 4) * 8;
#pragma unroll
            for (int mi = 0; mi < 4; mi++) {
                const __half* pa = S + (wm + mi * 16 + arow) * AST5 + acol;
                ldsm_x4(ah[mi], sm_u32(pa));
            }
            const int brow = ks * 16 + (lane & 15);
#pragma unroll
            for (int half = 0; half < 2; half++) {
                uint32_t bh[2][4];
#pragma unroll
                for (int np = 0; np < 2; np++) {
                    int bcol = wn + (half * 2 + np) * 16 + (lane >> 4) * 8;
                    ldsm_x4t(bh[np], sm_u32(S + SBH5 + brow * BST5 + bcol));
                }
#pragma unroll
                for (int mi = 0; mi < 4; mi++) {
#pragma unroll
                    for (int n4 = 0; n4 < 4; n4++) {
                        mma_f16(acc[mi][half * 4 + n4], ah[mi],
                                bh[n4 >> 1][(n4 & 1) * 2],
                                bh[n4 >> 1][(n4 & 1) * 2 + 1]);
                    }
                }
            }
        }
        __syncthreads();
    }

    // ---- epilogue ----
    __half* Dh = (region == 0) ? g_Qh : (region == 1) ? g_Kh : g_Vh;
    const float QS = 1.4426950408889634f / 128.0f;

#pragma unroll
    for (int mi = 0; mi < 4; mi++) {
#pragma unroll
        for (int ni = 0; ni < 8; ni++) {
            int row0 = bm + wm + mi * 16 + (lane >> 2);
            int colL = bnl + wn + ni * 8 + (lane & 3) * 2;
            float2 bb = *(const float2*)(bias + colL);
            float f0 = acc[mi][ni][0] + bb.x, f1 = acc[mi][ni][1] + bb.y;
            float f2 = acc[mi][ni][2] + bb.x, f3 = acc[mi][ni][3] + bb.y;
            if (job == 0) {
                *(float2*)(out + (size_t)row0 * DIMM + colL)       = make_float2(f0, f1);
                *(float2*)(out + (size_t)(row0 + 8) * DIMM + colL) = make_float2(f2, f3);
            } else {
                if (region <= 1) {   // rope for Q and K
                    int i = (colL & 127) >> 1;
                    float2 cs0 = g_rt[(row0 & (SEQ - 1)) * 64 + i];
                    float2 cs1 = g_rt[((row0 + 8) & (SEQ - 1)) * 64 + i];
                    float t0 = f0 * cs0.x - f1 * cs0.y;
                    float t1 = f1 * cs0.x + f0 * cs0.y;
                    float t2 = f2 * cs1.x - f3 * cs1.y;
                    float t3 = f3 * cs1.x + f2 * cs1.y;
                    if (region == 0) { t0 *= QS; t1 *= QS; t2 *= QS; t3 *= QS; }
                    f0 = t0; f1 = t1; f2 = t2; f3 = t3;
                }
                *(uint32_t*)(Dh + (size_t)row0 * DIMM + colL)       = packh2(f0, f1);
                *(uint32_t*)(Dh + (size_t)(row0 + 8) * DIMM + colL) = packh2(f2, f3);
            }
        }
    }
}

// ---------------------------------------------------------------------------
// fp16 flash attention: S = Q K^T (1 mma), O = P V (1 mma).
// BR=128 (8 warps x 16 rows), BC=64, d=128, 256 threads.
// smem: Q[0:32K) + 2 stages of {K 16K, V 16K} = 96KB total.
// ---------------------------------------------------------------------------
#define FQH 0u
#define FST(s) (32768u + (uint32_t)(s) * 32768u)
#define FLASH_SMEM 98304

__device__ __forceinline__ uint32_t fswz(uint32_t row, uint32_t colbyte) {
    uint32_t off = row * 256u + colbyte;
    return off ^ ((row & 7u) << 4);
}

__device__ __forceinline__ void flash_load_kv(
    uint32_t sb, int stage, size_t kb,
    const __half* __restrict__ Kh_, const __half* __restrict__ Vh_, int tid)
{
    uint32_t base = sb + FST(stage);
#pragma unroll
    for (int c = tid; c < 1024; c += 256) {
        uint32_t row = c >> 4, ch = c & 15;
        uint32_t d = fswz(row, ch * 16);
        size_t so = kb + (size_t)row * DIMM + ch * 8;
        cp16(base + d,          Kh_ + so);
        cp16(base + 16384u + d, Vh_ + so);
    }
}

__global__ __launch_bounds__(256) void flash_tc(
    const __half* __restrict__ Qh_, const __half* __restrict__ Kh_,
    const __half* __restrict__ Vh_, __half* __restrict__ Ah)
{
    const uint32_t sb = sm_u32(gsm);
    const int tid  = threadIdx.x;
    const int lane = tid & 31;
    const int wid  = tid >> 5;
    const int wr   = wid * 16;
    const int bh   = blockIdx.y;
    const int b    = bh >> 4;
    const int h    = bh & 15;
    const int q0   = blockIdx.x * 128;

    const size_t qg = (size_t)(b * SEQ + q0) * DIMM + h * HDIM;
    const size_t kg0 = (size_t)(b * SEQ) * DIMM + h * HDIM;

#pragma unroll
    for (int c = tid; c < 1024; c += 256) {
        uint32_t row = c >> 3, ch = c & 7;
        uint32_t d = fswz(row, ch * 16 + ((c & 8) ? 128u : 0u));
        // NOTE: 1024 iterations cover 128 rows x 16 chunks of 16B? Simpler below.
        (void)row; (void)ch; (void)d;
        break;
    }
    // Q tile load (128 rows x 256 bytes), swizzled
#pragma unroll
    for (int c = tid; c < 1024; c += 256) {
        uint32_t row = c >> 3, ch = c & 7;
        // 8 chunks of 16B cover only 128B; need 16 chunks -> use 2 passes
        uint32_t d0 = fswz(row, ch * 16);
        uint32_t d1 = fswz(row, ch * 16 + 128u);
        size_t so = qg + (size_t)row * DIMM + ch * 8;
        cp16(sb + FQH + d0, Qh_ + so);
        cp16(sb + FQH + d1, Qh_ + so + 64);
    }
    flash_load_kv(sb, 0, kg0, Kh_, Vh_, tid);
    asm volatile("cp.async.commit_group;" ::: "memory");

    float acc_o[16][4];
#pragma unroll
    for (int ni = 0; ni < 16; ni++)
#pragma unroll
        for (int e = 0; e < 4; e++) acc_o[ni][e] = 0.0f;
    float m_a = -INFINITY, m_b = -INFINITY, l_a = 0.0f, l_b = 0.0f;

    const uint32_t arow = (uint32_t)(wr + (lane & 15));
    const uint32_t chalf = (uint32_t)((lane >> 4) * 16);

    for (int kt = 0; kt < SEQ / 64; kt++) {
        asm volatile("cp.async.wait_group 0;" ::: "memory");
        __syncthreads();
        if (kt + 1 < SEQ / 64) {
            flash_load_kv(sb, (kt + 1) & 1, kg0 + (size_t)(kt + 1) * 64 * DIMM,
                          Kh_, Vh_, tid);
            asm volatile("cp.async.commit_group;" ::: "memory");
        }
        const uint32_t kbase = sb + FST(kt & 1);

        // ---- S = Q K^T (1 mma) ----
        float s[8][4];
#pragma unroll
        for (int j = 0; j < 8; j++)
#pragma unroll
            for (int e = 0; e < 4; e++) s[j][e] = 0.0f;

#pragma unroll
        for (int kc = 0; kc < 8; kc++) {
            uint32_t cb = (uint32_t)kc * 32 + chalf;
            uint32_t aq[4];
            ldsm_x4(aq, sb + FQH + fswz(arow, cb));
#pragma unroll
            for (int g = 0; g < 4; g++) {
                uint32_t krow = (uint32_t)(g * 16 + (lane & 15));
                uint32_t kh4[4];
                ldsm_x4(kh4, kbase + fswz(krow, cb));
                mma_f16(s[2 * g],     aq, kh4[0], kh4[2]);
                mma_f16(s[2 * g + 1], aq, kh4[1], kh4[3]);
            }
        }

        // ---- online softmax ----
        float mxa = -INFINITY, mxb = -INFINITY;
#pragma unroll
        for (int j = 0; j < 8; j++) {
            mxa = fmaxf(mxa, fmaxf(s[j][0], s[j][1]));
            mxb = fmaxf(mxb, fmaxf(s[j][2], s[j][3]));
        }
        mxa = fmaxf(mxa, __shfl_xor_sync(0xffffffffu, mxa, 1));
        mxa = fmaxf(mxa, __shfl_xor_sync(0xffffffffu, mxa, 2));
        mxb = fmaxf(mxb, __shfl_xor_sync(0xffffffffu, mxb, 1));
        mxb = fmaxf(mxb, __shfl_xor_sync(0xffffffffu, mxb, 2));

        float mna = fmaxf(m_a, mxa), mnb = fmaxf(m_b, mxb);
        float ca = fexp2(m_a - mna), cb2 = fexp2(m_b - mnb);
        m_a = mna; m_b = mnb;

        float sa = 0.0f, sbv = 0.0f;
        uint32_t ph[8][2];
#pragma unroll
        for (int j = 0; j < 8; j++) {
            float p0 = fexp2(s[j][0] - mna);
            float p1 = fexp2(s[j][1] - mna);
            float p2 = fexp2(s[j][2] - mnb);
            float p3 = fexp2(s[j][3] - mnb);
            sa  += p0 + p1;
            sbv += p2 + p3;
            ph[j][0] = packh2(p0, p1);
            ph[j][1] = packh2(p2, p3);
        }
        sa  += __shfl_xor_sync(0xffffffffu, sa, 1);
        sa  += __shfl_xor_sync(0xffffffffu, sa, 2);
        sbv += __shfl_xor_sync(0xffffffffu, sbv, 1);
        sbv += __shfl_xor_sync(0xffffffffu, sbv, 2);
        l_a = l_a * ca + sa;
        l_b = l_b * cb2 + sbv;

#pragma unroll
        for (int ni = 0; ni < 16; ni++) {
            acc_o[ni][0] *= ca;  acc_o[ni][1] *= ca;
            acc_o[ni][2] *= cb2; acc_o[ni][3] *= cb2;
        }

        // ---- O += P V (1 mma) ----
        const uint32_t vb = kbase + 16384u;
#pragma unroll
        for (int kc2 = 0; kc2 < 4; kc2++) {
            uint32_t aPh[4] = {ph[2 * kc2][0], ph[2 * kc2][1],
                               ph[2 * kc2 + 1][0], ph[2 * kc2 + 1][1]};
            uint32_t vrow = (uint32_t)(kc2 * 16 + (lane & 15));
#pragma unroll
            for (int nd = 0; nd < 8; nd++) {
                uint32_t cb = (uint32_t)nd * 32 + chalf;
                uint32_t vh4[4];
                ldsm_x4t(vh4, vb + fswz(vrow, cb));
                mma_f16(acc_o[2 * nd],     aPh, vh4[0], vh4[1]);
                mma_f16(acc_o[2 * nd + 1], aPh, vh4[2], vh4[3]);
            }
        }
    }

    // ---- epilogue: normalize, fp16 store ----
    float inva = __fdividef(1.0f, l_a);
    float invb = __fdividef(1.0f, l_b);
    int gr = lane >> 2, c2 = (lane & 3) * 2;
    size_t oa = (size_t)(b * SEQ + q0 + wr + gr) * DIMM + h * HDIM;
    size_t ob = oa + (size_t)8 * DIMM;
#pragma unroll
    for (int ni = 0; ni < 16; ni++) {
        int col = ni * 8 + c2;
        *(uint32_t*)&Ah[oa + col] = packh2(acc_o[ni][0] * inva, acc_o[ni][1] * inva);
        *(uint32_t*)&Ah[ob + col] = packh2(acc_o[ni][2] * invb, acc_o[ni][3] * invb);
    }
}

// ---------------------------------------------------------------------------
extern "C" void kernel_launch(void* const* d_in, const int* in_sizes, int n_in,
                              void* d_out, int out_size)
{
    const float* x  = (const float*)d_in[0];
    const float* Wq = (const float*)d_in[1];
    const float* bq = (const float*)d_in[2];
    const float* Wk = (const float*)d_in[3];
    const float* bk = (const float*)d_in[4];
    const float* Wv = (const float*)d_in[5];
    const float* bv = (const float*)d_in[6];
    const float* Wo = (const float*)d_in[7];
    const float* bo = (const float*)d_in[8];
    float* out = (float*)d_out;

    __half *x16, *w, *qh, *kh, *vh, *ah;
    cudaGetSymbolAddress((void**)&x16, g_x16);
    cudaGetSymbolAddress((void**)&w,   g_W);
    cudaGetSymbolAddress((void**)&qh,  g_Qh);
    cudaGetSymbolAddress((void**)&kh,  g_Kh);
    cudaGetSymbolAddress((void**)&vh,  g_Vh);
    cudaGetSymbolAddress((void**)&ah,  g_Ah);

    cudaFuncSetAttribute(tc5_gemm,
                         cudaFuncAttributeMaxDynamicSharedMemorySize, GM5_SMEM);
    cudaFuncSetAttribute(flash_tc,
                         cudaFuncAttributeMaxDynamicSharedMemorySize, FLASH_SMEM);

    const int NX = MTOK * DIMM;
    const int NW = DIMM * DIMM;

    convert_kernel<<<NX / 4 / 256, 256>>>(x, x16, NX);
    convert_kernel<<<NW / 4 / 256, 256>>>(Wq, w + 0 * WSZ, NW);
    convert_kernel<<<NW / 4 / 256, 256>>>(Wk, w + 1 * WSZ, NW);
    convert_kernel<<<NW / 4 / 256, 256>>>(Wv, w + 2 * WSZ, NW);
    convert_kernel<<<NW / 4 / 256, 256>>>(Wo, w + 3 * WSZ, NW);
    rope_table_kernel<<<(SEQ * 64) / 256, 256>>>();

    // Fused Q/K/V projection + bias + RoPE + fp16 pack
    tc5_gemm<<<dim3(3 * DIMM / 256, MTOK / 128), 256, GM5_SMEM>>>(
        x16, w, bq, bk, bv, bo, nullptr, 1);

    flash_tc<<<dim3(SEQ / 128, BATCH * NHEAD), 256, FLASH_SMEM>>>(
        qh, kh, vh, ah);

    // Output projection (fp32 + bias)
    tc5_gemm<<<dim3(DIMM / 256, MTOK / 128), 256, GM5_SMEM>>>(
        ah, w, bq, bk, bv, bo, out, 0);
}